// round 1
// baseline (speedup 1.0000x reference)
#include <cuda_runtime.h>
#include <math_constants.h>

// Chamfer loss: N=8 batches, V=4096 points, C=3.
// loss = mean_n [ mean_i min_j d(x_i,y_j) + mean_j min_i d(x_i,y_j) ]
//
// Gram trick: min_j ||q - t_j||^2 = 2*w_q - 2*max_j (q . t_j - w_tj),
// where w_p = 0.5*||p||^2. Inner loop = 3 FFMA + 1 FMAX per pair.

#define NB 8
#define VPTS 4096
#define THREADS 128
#define PTS 2
#define PTS_PER_BLOCK (THREADS * PTS)       // 256
#define QBLOCKS (VPTS / PTS_PER_BLOCK)      // 16
#define TOTAL_BLOCKS (QBLOCKS * NB * 2)     // 256

__device__ float4 g_xp[NB * VPTS];
__device__ float4 g_yp[NB * VPTS];
__device__ float  g_partial[TOTAL_BLOCKS];

// Pack (x,y,z) -> float4(x,y,z, 0.5*(x^2+y^2+z^2))
__global__ void pack_kernel(const float* __restrict__ x,
                            const float* __restrict__ y) {
    int i = blockIdx.x * blockDim.x + threadIdx.x;  // 0 .. 2*NB*VPTS-1
    if (i < NB * VPTS) {
        float a = x[3 * i], b = x[3 * i + 1], c = x[3 * i + 2];
        g_xp[i] = make_float4(a, b, c, 0.5f * (a * a + b * b + c * c));
    } else {
        int k = i - NB * VPTS;
        float a = y[3 * k], b = y[3 * k + 1], c = y[3 * k + 2];
        g_yp[k] = make_float4(a, b, c, 0.5f * (a * a + b * b + c * c));
    }
}

extern __shared__ float4 sT[];  // 4096 * 16B = 64 KB target tile

__global__ __launch_bounds__(THREADS)
void chamfer_main() {
    const int dir = blockIdx.z;             // 0: query=x,target=y ; 1: swapped
    const int n   = blockIdx.y;
    const float4* __restrict__ Q = dir ? g_yp : g_xp;
    const float4* __restrict__ T = dir ? g_xp : g_yp;

    // Stage the full target set for this batch in shared memory.
    #pragma unroll
    for (int j = threadIdx.x; j < VPTS; j += THREADS)
        sT[j] = T[n * VPTS + j];
    __syncthreads();

    // Each thread owns 2 query points (coalesced: tid and tid+THREADS).
    const int qi = n * VPTS + blockIdx.x * PTS_PER_BLOCK + threadIdx.x;
    const float4 q0 = Q[qi];
    const float4 q1 = Q[qi + THREADS];

    float m0 = -CUDART_INF_F;
    float m1 = -CUDART_INF_F;

    #pragma unroll 8
    for (int j = 0; j < VPTS; j++) {
        const float4 t = sT[j];   // broadcast across warp: conflict-free
        float s0 = fmaf(q0.x, t.x, fmaf(q0.y, t.y, fmaf(q0.z, t.z, -t.w)));
        float s1 = fmaf(q1.x, t.x, fmaf(q1.y, t.y, fmaf(q1.z, t.z, -t.w)));
        m0 = fmaxf(m0, s0);
        m1 = fmaxf(m1, s1);
    }

    // min squared distance = 2*(w_q - m); clamp (fp rounding) then sqrt.
    float d0 = sqrtf(fmaxf(2.0f * (q0.w - m0), 0.0f));
    float d1 = sqrtf(fmaxf(2.0f * (q1.w - m1), 0.0f));
    float sum = d0 + d1;

    // Block-reduce (deterministic), write per-block partial.
    #pragma unroll
    for (int off = 16; off > 0; off >>= 1)
        sum += __shfl_down_sync(0xffffffffu, sum, off);

    __shared__ float warpsum[THREADS / 32];
    if ((threadIdx.x & 31) == 0) warpsum[threadIdx.x >> 5] = sum;
    __syncthreads();

    if (threadIdx.x == 0) {
        float b = 0.0f;
        #pragma unroll
        for (int w = 0; w < THREADS / 32; w++) b += warpsum[w];
        int bflat = (blockIdx.z * gridDim.y + blockIdx.y) * gridDim.x + blockIdx.x;
        g_partial[bflat] = b;
    }
}

__global__ void reduce_kernel(float* __restrict__ out) {
    const int t = threadIdx.x;              // 256 threads == TOTAL_BLOCKS
    float v = g_partial[t];
    #pragma unroll
    for (int off = 16; off > 0; off >>= 1)
        v += __shfl_down_sync(0xffffffffu, v, off);

    __shared__ float ws[8];
    if ((t & 31) == 0) ws[t >> 5] = v;
    __syncthreads();

    if (t == 0) {
        float s = 0.0f;
        #pragma unroll
        for (int i = 0; i < 8; i++) s += ws[i];
        out[0] = s * (1.0f / (float)(NB * VPTS));  // both direction means + batch mean
    }
}

extern "C" void kernel_launch(void* const* d_in, const int* in_sizes, int n_in,
                              void* d_out, int out_size) {
    const float* x = (const float*)d_in[0];
    const float* y = (const float*)d_in[1];
    float* out = (float*)d_out;

    pack_kernel<<<(2 * NB * VPTS) / 256, 256>>>(x, y);

    cudaFuncSetAttribute(chamfer_main,
                         cudaFuncAttributeMaxDynamicSharedMemorySize,
                         VPTS * (int)sizeof(float4));
    dim3 grid(QBLOCKS, NB, 2);
    chamfer_main<<<grid, THREADS, VPTS * sizeof(float4)>>>();

    reduce_kernel<<<1, TOTAL_BLOCKS>>>(out);
}

// round 2
// speedup vs baseline: 1.4096x; 1.4096x over previous
#include <cuda_runtime.h>
#include <math_constants.h>

// Chamfer loss: N=8, V=4096, C=3.
// min_j ||q - t_j||^2 = 2*w_q - 2*max_j (q . t_j - w_tj),  w_p = 0.5*||p||^2.
// Inner loop uses packed fp32x2 FFMA (2 targets per instruction).

#define NB 8
#define VPTS 4096
#define THREADS 128
#define PTS 2
#define PTS_PER_BLOCK (THREADS * PTS)       // 256
#define QBLOCKS (VPTS / PTS_PER_BLOCK)      // 16
#define TOTAL_BLOCKS (QBLOCKS * NB * 2)     // 256

__device__ float g_partial[TOTAL_BLOCKS];

typedef unsigned long long u64;

__device__ __forceinline__ u64 dup2(float v) {
    u64 r;
    asm("mov.b64 %0, {%1, %1};" : "=l"(r) : "f"(v));
    return r;
}
__device__ __forceinline__ u64 ffma2(u64 a, u64 b, u64 c) {
    u64 d;
    asm("fma.rn.f32x2 %0, %1, %2, %3;" : "=l"(d) : "l"(a), "l"(b), "l"(c));
    return d;
}
__device__ __forceinline__ void maxacc(float& ml, float& mh, u64 s) {
    float lo, hi;
    asm("mov.b64 {%0, %1}, %2;" : "=f"(lo), "=f"(hi) : "l"(s));
    ml = fmaxf(ml, lo);
    mh = fmaxf(mh, hi);
}

// Shared: SoA target arrays so consecutive targets pack into f32x2.
// sTx | sTy | sTz | sTw(= -0.5*||t||^2), each VPTS floats -> 64 KB.
extern __shared__ float smem[];

__global__ __launch_bounds__(THREADS)
void chamfer_main(const float* __restrict__ x, const float* __restrict__ y) {
    const int dir = blockIdx.z;             // 0: query=x,target=y ; 1: swapped
    const int n   = blockIdx.y;
    const float* __restrict__ Q = dir ? y : x;
    const float* __restrict__ T = dir ? x : y;

    float* sTx = smem;
    float* sTy = smem + VPTS;
    float* sTz = smem + 2 * VPTS;
    float* sTw = smem + 3 * VPTS;

    // Stage + pack the full target set for this batch (w negated).
    const float* Tb = T + (size_t)n * VPTS * 3;
    for (int p = threadIdx.x; p < VPTS; p += THREADS) {
        float a = Tb[3 * p], b = Tb[3 * p + 1], c = Tb[3 * p + 2];
        sTx[p] = a; sTy[p] = b; sTz[p] = c;
        sTw[p] = -0.5f * (a * a + b * b + c * c);
    }
    __syncthreads();

    // Each thread owns PTS=2 query points (tid and tid+THREADS).
    const int q0i = (n * VPTS + blockIdx.x * PTS_PER_BLOCK + threadIdx.x) * 3;
    u64 qx2[PTS], qy2[PTS], qz2[PTS];
    float qw[PTS];
    #pragma unroll
    for (int p = 0; p < PTS; p++) {
        float a = Q[q0i + p * THREADS * 3];
        float b = Q[q0i + p * THREADS * 3 + 1];
        float c = Q[q0i + p * THREADS * 3 + 2];
        qx2[p] = dup2(a); qy2[p] = dup2(b); qz2[p] = dup2(c);
        qw[p] = 0.5f * (a * a + b * b + c * c);
    }

    // 4 max accumulators per query (targets mod 4), start at -inf.
    float mAl[PTS], mAh[PTS], mBl[PTS], mBh[PTS];
    #pragma unroll
    for (int p = 0; p < PTS; p++) {
        mAl[p] = mAh[p] = mBl[p] = mBh[p] = -CUDART_INF_F;
    }

    #pragma unroll 4
    for (int j = 0; j < VPTS; j += 4) {
        const ulonglong2 tx = *reinterpret_cast<const ulonglong2*>(sTx + j);
        const ulonglong2 ty = *reinterpret_cast<const ulonglong2*>(sTy + j);
        const ulonglong2 tz = *reinterpret_cast<const ulonglong2*>(sTz + j);
        const ulonglong2 tw = *reinterpret_cast<const ulonglong2*>(sTw + j);
        #pragma unroll
        for (int p = 0; p < PTS; p++) {
            u64 sA = ffma2(qz2[p], tz.x, tw.x);
            sA = ffma2(qy2[p], ty.x, sA);
            sA = ffma2(qx2[p], tx.x, sA);
            maxacc(mAl[p], mAh[p], sA);
            u64 sB = ffma2(qz2[p], tz.y, tw.y);
            sB = ffma2(qy2[p], ty.y, sB);
            sB = ffma2(qx2[p], tx.y, sB);
            maxacc(mBl[p], mBh[p], sB);
        }
    }

    float sum = 0.0f;
    #pragma unroll
    for (int p = 0; p < PTS; p++) {
        float m = fmaxf(fmaxf(mAl[p], mAh[p]), fmaxf(mBl[p], mBh[p]));
        sum += sqrtf(fmaxf(2.0f * (qw[p] - m), 0.0f));
    }

    // Deterministic block reduction -> per-block partial.
    #pragma unroll
    for (int off = 16; off > 0; off >>= 1)
        sum += __shfl_down_sync(0xffffffffu, sum, off);

    __shared__ float warpsum[THREADS / 32];
    if ((threadIdx.x & 31) == 0) warpsum[threadIdx.x >> 5] = sum;
    __syncthreads();

    if (threadIdx.x == 0) {
        float b = 0.0f;
        #pragma unroll
        for (int w = 0; w < THREADS / 32; w++) b += warpsum[w];
        int bflat = (blockIdx.z * gridDim.y + blockIdx.y) * gridDim.x + blockIdx.x;
        g_partial[bflat] = b;
    }
}

__global__ void reduce_kernel(float* __restrict__ out) {
    const int t = threadIdx.x;              // 256 threads == TOTAL_BLOCKS
    float v = g_partial[t];
    #pragma unroll
    for (int off = 16; off > 0; off >>= 1)
        v += __shfl_down_sync(0xffffffffu, v, off);

    __shared__ float ws[8];
    if ((t & 31) == 0) ws[t >> 5] = v;
    __syncthreads();

    if (t == 0) {
        float s = 0.0f;
        #pragma unroll
        for (int i = 0; i < 8; i++) s += ws[i];
        out[0] = s * (1.0f / (float)(NB * VPTS));
    }
}

extern "C" void kernel_launch(void* const* d_in, const int* in_sizes, int n_in,
                              void* d_out, int out_size) {
    const float* x = (const float*)d_in[0];
    const float* y = (const float*)d_in[1];
    float* out = (float*)d_out;

    cudaFuncSetAttribute(chamfer_main,
                         cudaFuncAttributeMaxDynamicSharedMemorySize,
                         4 * VPTS * (int)sizeof(float));
    dim3 grid(QBLOCKS, NB, 2);
    chamfer_main<<<grid, THREADS, 4 * VPTS * sizeof(float)>>>(x, y);

    reduce_kernel<<<1, TOTAL_BLOCKS>>>(out);
}

// round 3
// speedup vs baseline: 1.4602x; 1.0359x over previous
#include <cuda_runtime.h>
#include <math_constants.h>

// Chamfer loss: N=8, V=4096, C=3.
// min_j ||q - t_j||^2 = 2*w_q - 2*max_j (q . t_j - w_tj),  w_p = 0.5*||p||^2.
// Packed fp32x2 FFMA inner loop. Target dim split 4-way for load balance
// (1024 blocks ~= 7/SM, imbalance ~1%). Cross-block max combine + final
// reduction fused into the single kernel via counters (deterministic:
// fixed-order arithmetic, only the executing block varies).

#define NB 8
#define VPTS 4096
#define THREADS 128
#define PTS 2
#define QCHUNK (THREADS * PTS)          // 256 queries per block
#define NQ (VPTS / QCHUNK)              // 16
#define TSPLIT 4
#define TCHUNK (VPTS / TSPLIT)          // 1024 targets per block
#define NCHUNKS (2 * NB * NQ)           // 256 query chunks
#define NQTOT (2 * NB * VPTS)           // 65536 queries

__device__ float    g_pmax[NQTOT * TSPLIT];   // [qflat][tchunk]
__device__ unsigned g_cnt[NCHUNKS];           // zero-init; reset after use
__device__ float    g_qpart[NCHUNKS];
__device__ unsigned g_cnt_final;              // zero-init; reset after use

typedef unsigned long long u64;

__device__ __forceinline__ u64 dup2(float v) {
    u64 r;
    asm("mov.b64 %0, {%1, %1};" : "=l"(r) : "f"(v));
    return r;
}
__device__ __forceinline__ u64 ffma2(u64 a, u64 b, u64 c) {
    u64 d;
    asm("fma.rn.f32x2 %0, %1, %2, %3;" : "=l"(d) : "l"(a), "l"(b), "l"(c));
    return d;
}
__device__ __forceinline__ void maxacc(float& ml, float& mh, u64 s) {
    float lo, hi;
    asm("mov.b64 {%0, %1}, %2;" : "=f"(lo), "=f"(hi) : "l"(s));
    ml = fmaxf(ml, lo);
    mh = fmaxf(mh, hi);
}

// SoA target tile: sTx | sTy | sTz | sTw(= -0.5*||t||^2), TCHUNK floats each = 16KB
extern __shared__ float smem[];

__global__ __launch_bounds__(THREADS)
void chamfer_fused(const float* __restrict__ x, const float* __restrict__ y,
                   float* __restrict__ out) {
    const int qc  = blockIdx.x / TSPLIT;    // query chunk within batch: 0..15
    const int tc  = blockIdx.x % TSPLIT;    // target chunk: 0..3
    const int n   = blockIdx.y;
    const int dir = blockIdx.z;             // 0: query=x,target=y ; 1: swapped
    const float* __restrict__ Q = dir ? y : x;
    const float* __restrict__ T = dir ? x : y;
    const int tid = threadIdx.x;

    float* sTx = smem;
    float* sTy = smem + TCHUNK;
    float* sTz = smem + 2 * TCHUNK;
    float* sTw = smem + 3 * TCHUNK;

    // Stage + pack this block's target chunk (w negated).
    const float* Tb = T + ((size_t)n * VPTS + tc * TCHUNK) * 3;
    #pragma unroll
    for (int p = tid; p < TCHUNK; p += THREADS) {
        float a = Tb[3 * p], b = Tb[3 * p + 1], c = Tb[3 * p + 2];
        sTx[p] = a; sTy[p] = b; sTz[p] = c;
        sTw[p] = -0.5f * (a * a + b * b + c * c);
    }
    __syncthreads();

    // Each thread owns PTS=2 query points (tid and tid+THREADS).
    const int qbase = n * VPTS + qc * QCHUNK + tid;   // within this direction's set
    u64 qx2[PTS], qy2[PTS], qz2[PTS];
    float qw[PTS];
    #pragma unroll
    for (int p = 0; p < PTS; p++) {
        const float* qp = Q + (size_t)(qbase + p * THREADS) * 3;
        float a = qp[0], b = qp[1], c = qp[2];
        qx2[p] = dup2(a); qy2[p] = dup2(b); qz2[p] = dup2(c);
        qw[p] = 0.5f * (a * a + b * b + c * c);
    }

    float mAl[PTS], mAh[PTS], mBl[PTS], mBh[PTS];
    #pragma unroll
    for (int p = 0; p < PTS; p++)
        mAl[p] = mAh[p] = mBl[p] = mBh[p] = -CUDART_INF_F;

    #pragma unroll 4
    for (int j = 0; j < TCHUNK; j += 4) {
        const ulonglong2 tx = *reinterpret_cast<const ulonglong2*>(sTx + j);
        const ulonglong2 ty = *reinterpret_cast<const ulonglong2*>(sTy + j);
        const ulonglong2 tz = *reinterpret_cast<const ulonglong2*>(sTz + j);
        const ulonglong2 tw = *reinterpret_cast<const ulonglong2*>(sTw + j);
        #pragma unroll
        for (int p = 0; p < PTS; p++) {
            u64 sA = ffma2(qz2[p], tz.x, tw.x);
            sA = ffma2(qy2[p], ty.x, sA);
            sA = ffma2(qx2[p], tx.x, sA);
            maxacc(mAl[p], mAh[p], sA);
            u64 sB = ffma2(qz2[p], tz.y, tw.y);
            sB = ffma2(qy2[p], ty.y, sB);
            sB = ffma2(qx2[p], tx.y, sB);
            maxacc(mBl[p], mBh[p], sB);
        }
    }

    // Per-query partial max for this target chunk -> global.
    const int qflat0 = (dir * NB + n) * VPTS + qc * QCHUNK + tid;
    #pragma unroll
    for (int p = 0; p < PTS; p++) {
        float m = fmaxf(fmaxf(mAl[p], mAh[p]), fmaxf(mBl[p], mBh[p]));
        g_pmax[(size_t)(qflat0 + p * THREADS) * TSPLIT + tc] = m;
    }
    __threadfence();
    __syncthreads();

    // Elect the last-arriving of the TSPLIT blocks for this query chunk.
    const int chunk = (dir * NB + n) * NQ + qc;
    __shared__ bool isLastT;
    if (tid == 0)
        isLastT = (atomicAdd(&g_cnt[chunk], 1u) == TSPLIT - 1);
    __syncthreads();

    if (isLastT) {
        __threadfence();  // acquire: see the other 3 blocks' g_pmax writes
        float sum = 0.0f;
        #pragma unroll
        for (int p = 0; p < PTS; p++) {
            float4 m4 = reinterpret_cast<const float4*>(g_pmax)[qflat0 + p * THREADS];
            float m = fmaxf(fmaxf(m4.x, m4.y), fmaxf(m4.z, m4.w));
            sum += sqrtf(fmaxf(2.0f * (qw[p] - m), 0.0f));
        }
        // Deterministic block reduction.
        #pragma unroll
        for (int off = 16; off > 0; off >>= 1)
            sum += __shfl_down_sync(0xffffffffu, sum, off);
        __shared__ float warpsum[THREADS / 32];
        if ((tid & 31) == 0) warpsum[tid >> 5] = sum;
        __syncthreads();

        __shared__ bool isLastF;
        if (tid == 0) {
            float b = 0.0f;
            #pragma unroll
            for (int w = 0; w < THREADS / 32; w++) b += warpsum[w];
            g_qpart[chunk] = b;
            g_cnt[chunk] = 0;                 // reset for next launch
            __threadfence();
            isLastF = (atomicAdd(&g_cnt_final, 1u) == NCHUNKS - 1);
        }
        __syncthreads();

        if (isLastF) {
            __threadfence();
            // 256 chunk partials, 128 threads: 2 each, fixed order.
            float v = g_qpart[tid] + g_qpart[tid + THREADS];
            #pragma unroll
            for (int off = 16; off > 0; off >>= 1)
                v += __shfl_down_sync(0xffffffffu, v, off);
            __shared__ float ws2[THREADS / 32];
            if ((tid & 31) == 0) ws2[tid >> 5] = v;
            __syncthreads();
            if (tid == 0) {
                float s = 0.0f;
                #pragma unroll
                for (int w = 0; w < THREADS / 32; w++) s += ws2[w];
                out[0] = s * (1.0f / (float)(NB * VPTS));
                g_cnt_final = 0;              // reset for next launch
            }
        }
    }
}

extern "C" void kernel_launch(void* const* d_in, const int* in_sizes, int n_in,
                              void* d_out, int out_size) {
    const float* x = (const float*)d_in[0];
    const float* y = (const float*)d_in[1];
    float* out = (float*)d_out;

    dim3 grid(NQ * TSPLIT, NB, 2);   // 64 x 8 x 2 = 1024 blocks
    chamfer_fused<<<grid, THREADS, 4 * TCHUNK * sizeof(float)>>>(x, y, out);
}

// round 4
// speedup vs baseline: 1.5854x; 1.0858x over previous
#include <cuda_runtime.h>
#include <math_constants.h>

// Chamfer loss: N=8, V=4096, C=3.
// min_j ||q - t_j||^2 = 2*w_q - 2*max_j (q . t_j - w_tj),  w_p = 0.5*||p||^2.
// Packed fp32x2 FFMA inner loop, PTS=4 queries/thread (amortizes LDS),
// TSPLIT=8 target chunks -> 1024 blocks (~7/SM, ~1% imbalance).
// Cross-block combine + final reduction fused via counters (deterministic).

#define NB 8
#define VPTS 4096
#define THREADS 128
#define PTS 4
#define QCHUNK (THREADS * PTS)          // 512 queries per block
#define NQ (VPTS / QCHUNK)              // 8
#define TSPLIT 8
#define TCHUNK (VPTS / TSPLIT)          // 512 targets per block
#define NCHUNKS (2 * NB * NQ)           // 128 query chunks
#define NQTOT (2 * NB * VPTS)           // 65536 queries

__device__ float    g_pmax[NQTOT * TSPLIT];   // [qflat][tchunk]
__device__ unsigned g_cnt[NCHUNKS];           // zero-init; reset after use
__device__ float    g_qpart[NCHUNKS];
__device__ unsigned g_cnt_final;              // zero-init; reset after use

typedef unsigned long long u64;

__device__ __forceinline__ u64 dup2(float v) {
    u64 r;
    asm("mov.b64 %0, {%1, %1};" : "=l"(r) : "f"(v));
    return r;
}
__device__ __forceinline__ u64 ffma2(u64 a, u64 b, u64 c) {
    u64 d;
    asm("fma.rn.f32x2 %0, %1, %2, %3;" : "=l"(d) : "l"(a), "l"(b), "l"(c));
    return d;
}
__device__ __forceinline__ void maxacc(float& ml, float& mh, u64 s) {
    float lo, hi;
    asm("mov.b64 {%0, %1}, %2;" : "=f"(lo), "=f"(hi) : "l"(s));
    ml = fmaxf(ml, lo);
    mh = fmaxf(mh, hi);
}

// SoA target tile: sTx | sTy | sTz | sTw(= -0.5*||t||^2), TCHUNK floats each = 8KB
extern __shared__ float smem[];

__global__ __launch_bounds__(THREADS)
void chamfer_fused(const float* __restrict__ x, const float* __restrict__ y,
                   float* __restrict__ out) {
    const int qc  = blockIdx.x / TSPLIT;    // query chunk within batch: 0..NQ-1
    const int tc  = blockIdx.x % TSPLIT;    // target chunk: 0..TSPLIT-1
    const int n   = blockIdx.y;
    const int dir = blockIdx.z;             // 0: query=x,target=y ; 1: swapped
    const float* __restrict__ Q = dir ? y : x;
    const float* __restrict__ T = dir ? x : y;
    const int tid = threadIdx.x;

    float* sTx = smem;
    float* sTy = smem + TCHUNK;
    float* sTz = smem + 2 * TCHUNK;
    float* sTw = smem + 3 * TCHUNK;

    // Stage + pack this block's target chunk (w negated).
    const float* Tb = T + ((size_t)n * VPTS + tc * TCHUNK) * 3;
    #pragma unroll
    for (int p = tid; p < TCHUNK; p += THREADS) {
        float a = Tb[3 * p], b = Tb[3 * p + 1], c = Tb[3 * p + 2];
        sTx[p] = a; sTy[p] = b; sTz[p] = c;
        sTw[p] = -0.5f * (a * a + b * b + c * c);
    }
    __syncthreads();

    // Each thread owns PTS=4 query points (tid + p*THREADS).
    const int qbase = n * VPTS + qc * QCHUNK + tid;
    u64 qx2[PTS], qy2[PTS], qz2[PTS];
    float qw[PTS];
    #pragma unroll
    for (int p = 0; p < PTS; p++) {
        const float* qp = Q + (size_t)(qbase + p * THREADS) * 3;
        float a = qp[0], b = qp[1], c = qp[2];
        qx2[p] = dup2(a); qy2[p] = dup2(b); qz2[p] = dup2(c);
        qw[p] = 0.5f * (a * a + b * b + c * c);
    }

    float mAl[PTS], mAh[PTS], mBl[PTS], mBh[PTS];
    #pragma unroll
    for (int p = 0; p < PTS; p++)
        mAl[p] = mAh[p] = mBl[p] = mBh[p] = -CUDART_INF_F;

    #pragma unroll 2
    for (int j = 0; j < TCHUNK; j += 4) {
        const ulonglong2 tx = *reinterpret_cast<const ulonglong2*>(sTx + j);
        const ulonglong2 ty = *reinterpret_cast<const ulonglong2*>(sTy + j);
        const ulonglong2 tz = *reinterpret_cast<const ulonglong2*>(sTz + j);
        const ulonglong2 tw = *reinterpret_cast<const ulonglong2*>(sTw + j);
        #pragma unroll
        for (int p = 0; p < PTS; p++) {
            u64 sA = ffma2(qz2[p], tz.x, tw.x);
            sA = ffma2(qy2[p], ty.x, sA);
            sA = ffma2(qx2[p], tx.x, sA);
            maxacc(mAl[p], mAh[p], sA);
            u64 sB = ffma2(qz2[p], tz.y, tw.y);
            sB = ffma2(qy2[p], ty.y, sB);
            sB = ffma2(qx2[p], tx.y, sB);
            maxacc(mBl[p], mBh[p], sB);
        }
    }

    // Per-query partial max for this target chunk -> global.
    const int qflat0 = (dir * NB + n) * VPTS + qc * QCHUNK + tid;
    #pragma unroll
    for (int p = 0; p < PTS; p++) {
        float m = fmaxf(fmaxf(mAl[p], mAh[p]), fmaxf(mBl[p], mBh[p]));
        g_pmax[(size_t)(qflat0 + p * THREADS) * TSPLIT + tc] = m;
    }
    __threadfence();
    __syncthreads();

    // Elect the last-arriving of the TSPLIT blocks for this query chunk.
    const int chunk = (dir * NB + n) * NQ + qc;
    __shared__ bool isLastT;
    if (tid == 0)
        isLastT = (atomicAdd(&g_cnt[chunk], 1u) == TSPLIT - 1);
    __syncthreads();

    if (isLastT) {
        __threadfence();  // acquire: see the other blocks' g_pmax writes
        float sum = 0.0f;
        #pragma unroll
        for (int p = 0; p < PTS; p++) {
            int q = qflat0 + p * THREADS;
            float4 a4 = reinterpret_cast<const float4*>(g_pmax)[2 * q];
            float4 b4 = reinterpret_cast<const float4*>(g_pmax)[2 * q + 1];
            float m = fmaxf(fmaxf(fmaxf(a4.x, a4.y), fmaxf(a4.z, a4.w)),
                            fmaxf(fmaxf(b4.x, b4.y), fmaxf(b4.z, b4.w)));
            sum += sqrtf(fmaxf(2.0f * (qw[p] - m), 0.0f));
        }
        // Deterministic block reduction.
        #pragma unroll
        for (int off = 16; off > 0; off >>= 1)
            sum += __shfl_down_sync(0xffffffffu, sum, off);
        __shared__ float warpsum[THREADS / 32];
        if ((tid & 31) == 0) warpsum[tid >> 5] = sum;
        __syncthreads();

        __shared__ bool isLastF;
        if (tid == 0) {
            float b = 0.0f;
            #pragma unroll
            for (int w = 0; w < THREADS / 32; w++) b += warpsum[w];
            g_qpart[chunk] = b;
            g_cnt[chunk] = 0;                 // reset for next launch
            __threadfence();
            isLastF = (atomicAdd(&g_cnt_final, 1u) == NCHUNKS - 1);
        }
        __syncthreads();

        if (isLastF) {
            __threadfence();
            // 128 chunk partials, 128 threads: 1 each, fixed order.
            float v = g_qpart[tid];
            #pragma unroll
            for (int off = 16; off > 0; off >>= 1)
                v += __shfl_down_sync(0xffffffffu, v, off);
            __shared__ float ws2[THREADS / 32];
            if ((tid & 31) == 0) ws2[tid >> 5] = v;
            __syncthreads();
            if (tid == 0) {
                float s = 0.0f;
                #pragma unroll
                for (int w = 0; w < THREADS / 32; w++) s += ws2[w];
                out[0] = s * (1.0f / (float)(NB * VPTS));
                g_cnt_final = 0;              // reset for next launch
            }
        }
    }
}

extern "C" void kernel_launch(void* const* d_in, const int* in_sizes, int n_in,
                              void* d_out, int out_size) {
    const float* x = (const float*)d_in[0];
    const float* y = (const float*)d_in[1];
    float* out = (float*)d_out;

    dim3 grid(NQ * TSPLIT, NB, 2);   // 64 x 8 x 2 = 1024 blocks
    chamfer_fused<<<grid, THREADS, 4 * TCHUNK * sizeof(float)>>>(x, y, out);
}